// round 16
// baseline (speedup 1.0000x reference)
#include <cuda_runtime.h>

#define EPS 1e-5f

typedef unsigned long long ull;

// ---------------- scratch (static device memory; no allocations) ----------------
static __device__ __align__(16) float g_x2[128 * 64 * 3136];          // 102.8 MB
static __device__ __align__(16) float g_gate[2 * 16 * 8 * 3136];      // 3.2 MB
static __device__ __align__(16) float g_gpart[4][2 * 16 * 8 * 3136];  // conv3d partials
static __device__ float g_psum[64 * 1024];
static __device__ float g_psq[64 * 1024];
static __device__ float g_scale[64];
static __device__ float g_bias[64];

// ---------------- helpers ----------------
__device__ __forceinline__ ull pack2(float a, float b) {
    ull r;
    asm("mov.b64 %0, {%1, %2};" : "=l"(r) : "r"(__float_as_uint(a)), "r"(__float_as_uint(b)));
    return r;
}
__device__ __forceinline__ void unpack2(ull v, float& a, float& b) {
    unsigned int ua, ub;
    asm("mov.b64 {%0, %1}, %2;" : "=r"(ua), "=r"(ub) : "l"(v));
    a = __uint_as_float(ua);
    b = __uint_as_float(ub);
}
__device__ __forceinline__ ull fma2(ull a, ull b, ull c) {
    ull d;
    asm("fma.rn.f32x2 %0, %1, %2, %3;" : "=l"(d) : "l"(a), "l"(b), "l"(c));
    return d;
}
// R2-proven accurate forms. MUFU.TANH / expf-composed tanh both FAILED the 1e-3
// threshold (R3: 2.7e-3, R4: 3.9e-3) — do not substitute; gate tanh must be tanhf.
__device__ __forceinline__ float sigmoid_exact(float x) {
    return 1.f / (1.f + __expf(-x));
}

// A tile (7-row): [4ch][9 rows][68 cols]; C tile (14-row): [4ch][16 rows][68].
// Interior pixel g at col 4+g, halo cols 3/60 always zero. Row 272B (odd x16B).
#define CH_STRIDE 612    // kernelA: 9*68
#define TILE_FLOATS 2456
#define CH16 1088        // kernelC: 16*68

__global__ void kNop() {}

// =====================================================================
// Kernel A: attn conv2d (4 heads, 3x3, C=64) -> sigmoid(relu(.)),
//           x2 = x * attn, BN partial sums.
// grid (128, 8) = 7-row tiles, block 128: 98 compute (1h x 4w).
// SMEM-SLIMMED: s_attn aliases the (dead) tile buffer after the mainloop,
// cutting smem 35.1 -> 28.9 KB => 7 blocks/SM instead of 6.
// =====================================================================
__global__ void __launch_bounds__(128) kernelA(const float* __restrict__ x,
                                               const float* __restrict__ attn_w,
                                               const float* __restrict__ attn_b) {
    __shared__ __align__(16) ull s_w[64][9][2];
    __shared__ __align__(16) float s_tile[2][TILE_FLOATS];
    // s_attn aliases s_tile[0] after the mainloop (4*392 = 1568 floats < 2456)

    const int n = blockIdx.x;
    const int h_base = blockIdx.y * 7;
    const int tid = threadIdx.x;

    for (int i = tid; i < 576; i += 128) {
        int c = i / 9, k = i - c * 9;
        s_w[c][k][0] = pack2(attn_w[c * 9 + k], attn_w[576 + c * 9 + k]);
        s_w[c][k][1] = pack2(attn_w[1152 + c * 9 + k], attn_w[1728 + c * 9 + k]);
    }
    for (int i = tid; i < 72; i += 128) {
        int buf = i / 36, rem = i - (i / 36) * 36;
        float* row = &s_tile[buf][rem * 68];
        row[3] = 0.f;
        row[60] = 0.f;
    }

    const int lr = tid / 14, cg = tid - (tid / 14) * 14;
    const bool lslot = tid < 126;
    const int gh = h_base - 1 + lr;
    const bool lvalid = lslot && ((unsigned)gh < 56u);
    const int goff = gh * 56 + cg * 4;
    const int soff = lr * 68 + 4 + cg * 4;

    const float* xn = x + n * 200704;
    const float4 z4 = make_float4(0.f, 0.f, 0.f, 0.f);
    float4 st[4] = {z4, z4, z4, z4};
    if (lvalid) {
#pragma unroll
        for (int cc = 0; cc < 4; cc++) st[cc] = *(const float4*)(xn + cc * 3136 + goff);
    }

    const bool active = tid < 98;
    const int hi = tid / 14, wi = tid - hi * 14;

    ull acc[4][2];
#pragma unroll
    for (int p = 0; p < 4; p++) { acc[p][0] = 0ull; acc[p][1] = 0ull; }

    for (int s = 0; s < 16; s++) {
        const int c0 = s * 4;
        float* tb = s_tile[s & 1];
        if (lslot) {
#pragma unroll
            for (int cc = 0; cc < 4; cc++) *(float4*)(tb + cc * CH_STRIDE + soff) = st[cc];
        }
        __syncthreads();
        if (s < 15 && lvalid) {
            const float* src = xn + (c0 + 4) * 3136 + goff;
#pragma unroll
            for (int cc = 0; cc < 4; cc++) st[cc] = *(const float4*)(src + cc * 3136);
        }
        if (active) {
#pragma unroll
            for (int cc = 0; cc < 4; cc++) {
#pragma unroll
                for (int r = 0; r < 3; r++) {
                    const float* rp = tb + cc * CH_STRIDE + (hi + r) * 68 + 4 + 4 * wi;
                    float4 q = *(const float4*)rp;
                    float vl = rp[-1], vr = rp[4];
                    ull p0 = pack2(vl, vl), p1 = pack2(q.x, q.x), p2 = pack2(q.y, q.y);
                    ull p3 = pack2(q.z, q.z), p4 = pack2(q.w, q.w), p5 = pack2(vr, vr);
                    ulonglong2 t0 = *(const ulonglong2*)&s_w[c0 + cc][r * 3 + 0][0];
                    ulonglong2 t1 = *(const ulonglong2*)&s_w[c0 + cc][r * 3 + 1][0];
                    ulonglong2 t2 = *(const ulonglong2*)&s_w[c0 + cc][r * 3 + 2][0];
                    ull wl, wh;
                    wl = t0.x; wh = t0.y;
                    acc[0][0] = fma2(p0, wl, acc[0][0]); acc[1][0] = fma2(p1, wl, acc[1][0]);
                    acc[2][0] = fma2(p2, wl, acc[2][0]); acc[3][0] = fma2(p3, wl, acc[3][0]);
                    acc[0][1] = fma2(p0, wh, acc[0][1]); acc[1][1] = fma2(p1, wh, acc[1][1]);
                    acc[2][1] = fma2(p2, wh, acc[2][1]); acc[3][1] = fma2(p3, wh, acc[3][1]);
                    wl = t1.x; wh = t1.y;
                    acc[0][0] = fma2(p1, wl, acc[0][0]); acc[1][0] = fma2(p2, wl, acc[1][0]);
                    acc[2][0] = fma2(p3, wl, acc[2][0]); acc[3][0] = fma2(p4, wl, acc[3][0]);
                    acc[0][1] = fma2(p1, wh, acc[0][1]); acc[1][1] = fma2(p2, wh, acc[1][1]);
                    acc[2][1] = fma2(p3, wh, acc[2][1]); acc[3][1] = fma2(p4, wh, acc[3][1]);
                    wl = t2.x; wh = t2.y;
                    acc[0][0] = fma2(p2, wl, acc[0][0]); acc[1][0] = fma2(p3, wl, acc[1][0]);
                    acc[2][0] = fma2(p4, wl, acc[2][0]); acc[3][0] = fma2(p5, wl, acc[3][0]);
                    acc[0][1] = fma2(p2, wh, acc[0][1]); acc[1][1] = fma2(p3, wh, acc[1][1]);
                    acc[2][1] = fma2(p4, wh, acc[2][1]); acc[3][1] = fma2(p5, wh, acc[3][1]);
                }
            }
        }
    }

    // s_tile is dead now; reuse buffer 0 for attn. Barrier separates the last
    // tile reads (above) from the attn writes (below).
    __syncthreads();
    float* s_attn = s_tile[0];  // [head*392 + px]

    if (active) {
        const int w0 = 4 * wi;
        float b0 = attn_b[0], b1 = attn_b[1], b2 = attn_b[2], b3v = attn_b[3];
#pragma unroll
        for (int p = 0; p < 4; p++) {
            float a0, a1, a2, a3;
            unpack2(acc[p][0], a0, a1);
            unpack2(acc[p][1], a2, a3);
            a0 = fmaxf(a0 + b0, 0.f);
            a1 = fmaxf(a1 + b1, 0.f);
            a2 = fmaxf(a2 + b2, 0.f);
            a3 = fmaxf(a3 + b3v, 0.f);
            int px = hi * 56 + w0 + p;
            s_attn[0 * 392 + px] = sigmoid_exact(a0);
            s_attn[1 * 392 + px] = sigmoid_exact(a1);
            s_attn[2 * 392 + px] = sigmoid_exact(a2);
            s_attn[3 * 392 + px] = sigmoid_exact(a3);
        }
    }
    __syncthreads();

    const int warp = tid >> 5, lane = tid & 31;
    const int pidx = n * 8 + blockIdx.y;
    for (int c = warp; c < 64; c += 4) {
        int head = c >> 4;
        const float4* xp = (const float4*)(xn + c * 3136 + h_base * 56);
        float4* x2p = (float4*)(g_x2 + n * 200704 + c * 3136 + h_base * 56);
        const float4* ap = (const float4*)&s_attn[head * 392];
        float sum = 0.f, sq = 0.f;
        for (int i = lane; i < 98; i += 32) {
            float4 xv = xp[i], av = ap[i];
            float4 v;
            v.x = xv.x * av.x;
            v.y = xv.y * av.y;
            v.z = xv.z * av.z;
            v.w = xv.w * av.w;
            x2p[i] = v;
            sum += (v.x + v.y) + (v.z + v.w);
            sq += (v.x * v.x + v.y * v.y) + (v.z * v.z + v.w * v.w);
        }
#pragma unroll
        for (int o = 16; o; o >>= 1) {
            sum += __shfl_down_sync(0xffffffffu, sum, o);
            sq += __shfl_down_sync(0xffffffffu, sq, o);
        }
        if (lane == 0) {
            g_psum[c * 1024 + pidx] = sum;
            g_psq[c * 1024 + pidx] = sq;
        }
    }
}

// =====================================================================
// Kernel B: reduce BN partials -> scale/bias. grid 64, block 32.
// =====================================================================
__global__ void kernelB(const float* __restrict__ gamma, const float* __restrict__ beta) {
    int c = blockIdx.x, lane = threadIdx.x;
    float s = 0.f, q = 0.f;
    for (int i = lane; i < 1024; i += 32) {
        s += g_psum[c * 1024 + i];
        q += g_psq[c * 1024 + i];
    }
#pragma unroll
    for (int o = 16; o; o >>= 1) {
        s += __shfl_down_sync(0xffffffffu, s, o);
        q += __shfl_down_sync(0xffffffffu, q, o);
    }
    if (lane == 0) {
        const float inv_n = 1.f / 401408.f;
        float mean = s * inv_n;
        float var = q * inv_n - mean * mean;
        float sc = gamma[c] * rsqrtf(var + EPS);
        g_scale[c] = sc;
        g_bias[c] = beta[c] - mean * sc;
    }
}

// ---------------- 8-wide conv helpers (C): per-row paired weight loads ----------------
__device__ __forceinline__ void load_wrow(const ull* wv, int r, ull* wr) {
    if (r == 0) {
        ulonglong2 a = *(const ulonglong2*)&wv[0];
        wr[0] = a.x; wr[1] = a.y; wr[2] = wv[2];
    } else if (r == 1) {
        wr[0] = wv[3];
        ulonglong2 a = *(const ulonglong2*)&wv[4];
        wr[1] = a.x; wr[2] = a.y;
    } else {
        ulonglong2 a = *(const ulonglong2*)&wv[6];
        wr[0] = a.x; wr[1] = a.y; wr[2] = wv[8];
    }
}

__device__ __forceinline__ void conv_pair8(const float* tb, const ull (*wt)[12],
                                           int hi, int wi, ull* acc) {
#pragma unroll
    for (int cc = 0; cc < 4; cc++) {
        const ull* wv = wt[cc];
#pragma unroll
        for (int r = 0; r < 3; r++) {
            const float* rp = tb + cc * CH16 + (hi + r) * 68 + 4 + 8 * wi;
            float4 q0 = *(const float4*)rp;
            float4 q1 = *(const float4*)(rp + 4);
            float vl = rp[-1], vr = rp[8];
            ull p[10];
            p[0] = pack2(vl, vl);
            p[1] = pack2(q0.x, q0.x); p[2] = pack2(q0.y, q0.y);
            p[3] = pack2(q0.z, q0.z); p[4] = pack2(q0.w, q0.w);
            p[5] = pack2(q1.x, q1.x); p[6] = pack2(q1.y, q1.y);
            p[7] = pack2(q1.z, q1.z); p[8] = pack2(q1.w, q1.w);
            p[9] = pack2(vr, vr);
            ull wr[3];
            load_wrow(wv, r, wr);
#pragma unroll
            for (int jw = 0; jw < 3; jw++) {
                ull w = wr[jw];
#pragma unroll
                for (int o = 0; o < 8; o++) acc[o] = fma2(p[o + jw], w, acc[o]);
            }
        }
    }
}

__device__ __forceinline__ void conv_two8(const float* tb, const ull (*wtA)[12],
                                          const ull (*wtB)[12], int hi, int wi,
                                          ull* accA, ull* accB) {
#pragma unroll
    for (int cc = 0; cc < 4; cc++) {
        const ull* wvA = wtA[cc];
        const ull* wvB = wtB[cc];
#pragma unroll
        for (int r = 0; r < 3; r++) {
            const float* rp = tb + cc * CH16 + (hi + r) * 68 + 4 + 8 * wi;
            float4 q0 = *(const float4*)rp;
            float4 q1 = *(const float4*)(rp + 4);
            float vl = rp[-1], vr = rp[8];
            ull p[10];
            p[0] = pack2(vl, vl);
            p[1] = pack2(q0.x, q0.x); p[2] = pack2(q0.y, q0.y);
            p[3] = pack2(q0.z, q0.z); p[4] = pack2(q0.w, q0.w);
            p[5] = pack2(q1.x, q1.x); p[6] = pack2(q1.y, q1.y);
            p[7] = pack2(q1.z, q1.z); p[8] = pack2(q1.w, q1.w);
            p[9] = pack2(vr, vr);
            ull wrA[3], wrB[3];
            load_wrow(wvA, r, wrA);
            load_wrow(wvB, r, wrB);
#pragma unroll
            for (int jw = 0; jw < 3; jw++) {
                ull wa = wrA[jw], wb = wrB[jw];
#pragma unroll
                for (int o = 0; o < 8; o++) accA[o] = fma2(p[o + jw], wa, accA[o]);
#pragma unroll
                for (int o = 0; o < 8; o++) accB[o] = fma2(p[o + jw], wb, accB[o]);
            }
        }
    }
}

// =====================================================================
// Kernel C: grouped conv3d partials on relu(bn(x2)). t-QUAD + 4-way
// CHANNEL-SPLIT (8 of 32 ch per block) + 14-row tiles, 1h x 8w/thread.
// grid (128 [b*8+quad*4+cs], 2 g, 4 hz) = 1024 blocks, block 128.
// (R15-proven, unchanged)
// =====================================================================
__global__ void __launch_bounds__(128) kernelC(const float* __restrict__ w3) {
    __shared__ __align__(16) ull s_wp[4][8][12];
    __shared__ __align__(16) float s_tile[2][4 * CH16 + 8];
    __shared__ float s_sc[8], s_bi[8];

    const int bx = blockIdx.x;
    const int b = bx >> 3;
    const int quad = (bx >> 2) & 1;
    const int cs = bx & 3;
    const int t0 = quad * 4;
    const int g = blockIdx.y;
    const int h_base = blockIdx.z * 14;
    const int tid = threadIdx.x;
    const int gbase_ch = g * 32 + cs * 8;

    for (int i = tid; i < 72; i += 128) {
        int c = i / 9, k = i - (i / 9) * 9;
        int base = g * 864 + (cs * 8 + c) * 27;
        float w0v = w3[base + k];
        float w1v = w3[base + 9 + k];
        float w2v = w3[base + 18 + k];
        s_wp[0][c][k] = pack2(w0v, 0.f);
        s_wp[1][c][k] = pack2(w1v, w0v);
        s_wp[2][c][k] = pack2(w2v, w1v);
        s_wp[3][c][k] = pack2(0.f, w2v);
    }
    if (tid < 8) {
        s_sc[tid] = g_scale[gbase_ch + tid];
        s_bi[tid] = g_bias[gbase_ch + tid];
    }
    for (int i = tid; i < 128; i += 128) {
        int buf = i >> 6, rem = i & 63;
        float* row = &s_tile[buf][rem * 68];
        row[3] = 0.f;
        row[60] = 0.f;
    }
    // CRITICAL: stage-0 tile-write reads s_sc/s_bi (written by tid<8 only).
    __syncthreads();

    const int r0 = tid / 14, cg0 = tid - (tid / 14) * 14;
    const int i1 = tid + 128;
    const bool slot1 = i1 < 224;
    const int r1 = i1 / 14, cg1 = i1 - (i1 / 14) * 14;
    const int gh0 = h_base - 1 + r0, gh1 = h_base - 1 + r1;
    const bool v0 = (unsigned)gh0 < 56u;
    const bool v1 = slot1 && ((unsigned)gh1 < 56u);
    const int go0 = gh0 * 56 + cg0 * 4, go1 = gh1 * 56 + cg1 * 4;
    const int so0 = r0 * 68 + 4 + cg0 * 4, so1 = r1 * 68 + 4 + cg1 * 4;

    const int i_lo = (t0 == 0) ? 1 : 0;
    const float4 z4 = make_float4(0.f, 0.f, 0.f, 0.f);
    float4 st0[4] = {z4, z4, z4, z4}, st1[4] = {z4, z4, z4, z4};
    {
        int ts = t0 - 1 + i_lo;
        const float* src = g_x2 + ((b * 8 + ts) * 64 + gbase_ch) * 3136;
#pragma unroll
        for (int cc = 0; cc < 4; cc++) {
            if (v0) st0[cc] = *(const float4*)(src + cc * 3136 + go0);
            if (v1) st1[cc] = *(const float4*)(src + cc * 3136 + go1);
        }
    }

    const bool active = tid < 98;
    const int hi = tid / 7, wi = tid - (tid / 7) * 7;

    ull accA[8], accB[8];
#pragma unroll
    for (int o = 0; o < 8; o++) { accA[o] = 0ull; accB[o] = 0ull; }

    for (int s = 0; s < 10; s++) {
        const int i_sl = i_lo + (s >> 1);
        const int c0 = (s & 1) * 4;
        float* tb = s_tile[s & 1];
#pragma unroll
        for (int cc = 0; cc < 4; cc++) {
            float sc = s_sc[c0 + cc], bi = s_bi[c0 + cc];
            float4 v = z4;
            if (v0) {
                v.x = fmaxf(fmaf(st0[cc].x, sc, bi), 0.f);
                v.y = fmaxf(fmaf(st0[cc].y, sc, bi), 0.f);
                v.z = fmaxf(fmaf(st0[cc].z, sc, bi), 0.f);
                v.w = fmaxf(fmaf(st0[cc].w, sc, bi), 0.f);
            }
            *(float4*)(tb + cc * CH16 + so0) = v;
            if (slot1) {
                float4 u = z4;
                if (v1) {
                    u.x = fmaxf(fmaf(st1[cc].x, sc, bi), 0.f);
                    u.y = fmaxf(fmaf(st1[cc].y, sc, bi), 0.f);
                    u.z = fmaxf(fmaf(st1[cc].z, sc, bi), 0.f);
                    u.w = fmaxf(fmaf(st1[cc].w, sc, bi), 0.f);
                }
                *(float4*)(tb + cc * CH16 + so1) = u;
            }
        }
        __syncthreads();
        if (s < 9) {
            int i_n = i_lo + ((s + 1) >> 1);
            int tsn = t0 - 1 + i_n;
            int c0n = ((s + 1) & 1) * 4;
            const float* src = g_x2 + ((b * 8 + tsn) * 64 + gbase_ch + c0n) * 3136;
#pragma unroll
            for (int cc = 0; cc < 4; cc++) {
                if (v0) st0[cc] = *(const float4*)(src + cc * 3136 + go0);
                if (v1) st1[cc] = *(const float4*)(src + cc * 3136 + go1);
            }
        }
        if (active) {
            const int jA = i_sl;
            const int jB = i_sl - 2;
            const bool aon = (jA <= 3), bon = (jB >= 0);
            if (aon && bon)
                conv_two8(tb, &s_wp[jA][c0], &s_wp[jB][c0], hi, wi, accA, accB);
            else if (aon)
                conv_pair8(tb, &s_wp[jA][c0], hi, wi, accA);
            else
                conv_pair8(tb, &s_wp[jB][c0], hi, wi, accB);
        }
    }

    if (active) {
        int hw = (h_base + hi) * 56 + 8 * wi;
        float* gp = g_gpart[cs] + (((g * 16 + b) * 8 + t0) * 3136 + hw);
        float oa0[8], oa1[8], ob0[8], ob1[8];
#pragma unroll
        for (int o = 0; o < 8; o++) {
            unpack2(accA[o], oa0[o], oa1[o]);
            unpack2(accB[o], ob0[o], ob1[o]);
        }
        *(float4*)(gp + 0) = make_float4(oa0[0], oa0[1], oa0[2], oa0[3]);
        *(float4*)(gp + 4) = make_float4(oa0[4], oa0[5], oa0[6], oa0[7]);
        *(float4*)(gp + 3136) = make_float4(oa1[0], oa1[1], oa1[2], oa1[3]);
        *(float4*)(gp + 3140) = make_float4(oa1[4], oa1[5], oa1[6], oa1[7]);
        *(float4*)(gp + 2 * 3136) = make_float4(ob0[0], ob0[1], ob0[2], ob0[3]);
        *(float4*)(gp + 2 * 3136 + 4) = make_float4(ob0[4], ob0[5], ob0[6], ob0[7]);
        *(float4*)(gp + 3 * 3136) = make_float4(ob1[0], ob1[1], ob1[2], ob1[3]);
        *(float4*)(gp + 3 * 3136 + 4) = make_float4(ob1[4], ob1[5], ob1[6], ob1[7]);
    }
}

// =====================================================================
// Kernel C2: gate = tanhf(sum of 4 partials + bias). grid 3136, block 256.
// =====================================================================
__global__ void __launch_bounds__(256) kernelC2(const float* __restrict__ b3) {
    int idx = blockIdx.x * 256 + threadIdx.x;
    int g = idx / 401408;
    float v = (g_gpart[0][idx] + g_gpart[1][idx]) +
              (g_gpart[2][idx] + g_gpart[3][idx]) + b3[g];
    g_gate[idx] = tanhf(v);
}

// =====================================================================
// Kernel D: gate apply + temporal shift + channel interleave, float4 streaming.
// =====================================================================
__global__ void __launch_bounds__(256) kernelD(float* __restrict__ out) {
    int idx = blockIdx.x * 256 + threadIdx.x;
    int w4 = idx % 14;
    int tmp = idx / 14;
    int h = tmp % 56;
    tmp /= 56;
    int c_out = tmp & 63;
    int b = tmp >> 6;

    int gsel = c_out >> 5;
    int cc = c_out & 31;
    int c_src = gsel * 32 + (cc & 1) * 16 + (cc >> 1);

    int hw = h * 56 + w4 * 4;
    const float4* gbase = (const float4*)(g_gate + ((gsel * 16 + b) * 8) * 3136 + hw);
    int xoff0 = (b * 8) * 64 * 3136 + c_src * 3136 + hw;
    int ooff0 = (b * 8) * 64 * 3136 + c_out * 3136 + hw;

    float4 py = make_float4(0.f, 0.f, 0.f, 0.f);
    if (gsel == 0) {
#pragma unroll
        for (int t = 7; t >= 0; --t) {
            float4 xt = *(const float4*)(g_x2 + xoff0 + t * 64 * 3136);
            float4 gt = gbase[t * 784];
            float4 o;
            o.x = py.x + (1.f - gt.x) * xt.x;
            o.y = py.y + (1.f - gt.y) * xt.y;
            o.z = py.z + (1.f - gt.z) * xt.z;
            o.w = py.w + (1.f - gt.w) * xt.w;
            *(float4*)(out + ooff0 + t * 64 * 3136) = o;
            py.x = gt.x * xt.x;
            py.y = gt.y * xt.y;
            py.z = gt.z * xt.z;
            py.w = gt.w * xt.w;
        }
    } else {
#pragma unroll
        for (int t = 0; t < 8; ++t) {
            float4 xt = *(const float4*)(g_x2 + xoff0 + t * 64 * 3136);
            float4 gt = gbase[t * 784];
            float4 o;
            o.x = py.x + (1.f - gt.x) * xt.x;
            o.y = py.y + (1.f - gt.y) * xt.y;
            o.z = py.z + (1.f - gt.z) * xt.z;
            o.w = py.w + (1.f - gt.w) * xt.w;
            *(float4*)(out + ooff0 + t * 64 * 3136) = o;
            py.x = gt.x * xt.x;
            py.y = gt.y * xt.y;
            py.z = gt.z * xt.z;
            py.w = gt.w * xt.w;
        }
    }
}

// =====================================================================
extern "C" void kernel_launch(void* const* d_in, const int* in_sizes, int n_in,
                              void* d_out, int out_size) {
    const float* x = (const float*)d_in[0];
    const float* attn_w = (const float*)d_in[1];
    const float* attn_b = (const float*)d_in[2];
    const float* gamma = (const float*)d_in[3];
    const float* beta = (const float*)d_in[4];
    const float* w3 = (const float*)d_in[5];
    const float* b3 = (const float*)d_in[6];
    float* out = (float*)d_out;

    // 3 nops: ncu (-s 5 -c 1, 2 harness pre-launches) captures kernelA
    kNop<<<1, 32>>>();
    kNop<<<1, 32>>>();
    kNop<<<1, 32>>>();
    kernelA<<<dim3(128, 8), 128>>>(x, attn_w, attn_b);
    kernelB<<<64, 32>>>(gamma, beta);
    kernelC<<<dim3(128, 2, 4), 128>>>(w3);
    kernelC2<<<3136, 256>>>(b3);
    kernelD<<<3136, 256>>>(out);
}

// round 17
// speedup vs baseline: 1.0503x; 1.0503x over previous
#include <cuda_runtime.h>

#define EPS 1e-5f

typedef unsigned long long ull;

// ---------------- scratch (static device memory; no allocations) ----------------
static __device__ __align__(16) float g_x2[128 * 64 * 3136];          // 102.8 MB
static __device__ __align__(16) float g_gate[2 * 16 * 8 * 3136];      // 3.2 MB
static __device__ __align__(16) float g_gpart[4][2 * 16 * 8 * 3136];  // conv3d partials
static __device__ float g_psum[64 * 1024];
static __device__ float g_psq[64 * 1024];
static __device__ float g_scale[64];
static __device__ float g_bias[64];

// ---------------- helpers ----------------
__device__ __forceinline__ ull pack2(float a, float b) {
    ull r;
    asm("mov.b64 %0, {%1, %2};" : "=l"(r) : "r"(__float_as_uint(a)), "r"(__float_as_uint(b)));
    return r;
}
__device__ __forceinline__ void unpack2(ull v, float& a, float& b) {
    unsigned int ua, ub;
    asm("mov.b64 {%0, %1}, %2;" : "=r"(ua), "=r"(ub) : "l"(v));
    a = __uint_as_float(ua);
    b = __uint_as_float(ub);
}
__device__ __forceinline__ ull fma2(ull a, ull b, ull c) {
    ull d;
    asm("fma.rn.f32x2 %0, %1, %2, %3;" : "=l"(d) : "l"(a), "l"(b), "l"(c));
    return d;
}
// R2-proven accurate forms. MUFU.TANH / expf-composed tanh both FAILED the 1e-3
// threshold (R3: 2.7e-3, R4: 3.9e-3) — do not substitute; gate tanh must be tanhf.
__device__ __forceinline__ float sigmoid_exact(float x) {
    return 1.f / (1.f + __expf(-x));
}

// A tile (7-row): [4ch][9 rows][68 cols]; C tile (14-row): [4ch][16 rows][68].
// Interior pixel g at col 4+g, halo cols 3/60 always zero. Row 272B (odd x16B).
#define CH_STRIDE 612    // kernelA: 9*68
#define TILE_FLOATS 2456
#define CH16 1088        // kernelC: 16*68

__global__ void kNop() {}

// =====================================================================
// Kernel A: attn conv2d (4 heads, 3x3, C=64) -> sigmoid(relu(.)),
//           x2 = x * attn, BN partial sums.
// grid (128, 8) = 7-row tiles, block 128.
// SHUFFLE-HALO layout: 16-lane rows (wi=tid&15, row=tid>>4); vl/vr come
// from lane shuffles instead of scalar LDS (-33% L1 ops). smem-slim alias.
// =====================================================================
__global__ void __launch_bounds__(128) kernelA(const float* __restrict__ x,
                                               const float* __restrict__ attn_w,
                                               const float* __restrict__ attn_b) {
    __shared__ __align__(16) ull s_w[64][9][2];
    __shared__ __align__(16) float s_tile[2][TILE_FLOATS];
    // s_attn aliases s_tile[0] after the mainloop (4*392 floats < 2456)

    const int n = blockIdx.x;
    const int h_base = blockIdx.y * 7;
    const int tid = threadIdx.x;

    for (int i = tid; i < 576; i += 128) {
        int c = i / 9, k = i - c * 9;
        s_w[c][k][0] = pack2(attn_w[c * 9 + k], attn_w[576 + c * 9 + k]);
        s_w[c][k][1] = pack2(attn_w[1152 + c * 9 + k], attn_w[1728 + c * 9 + k]);
    }
    // zero halo cols (3, 60) of all 4ch x 9 rows, both buffers.
    // col 60 doubles as the shuffle source for wi=13's vr (always 0).
    for (int i = tid; i < 72; i += 128) {
        int buf = i / 36, rem = i - (i / 36) * 36;
        float* row = &s_tile[buf][rem * 68];
        row[3] = 0.f;
        row[60] = 0.f;
    }

    // loader slots (unchanged mapping): 126 slots = 9r x 14cg, 4 channels each
    const int lr = tid / 14, cg = tid - (tid / 14) * 14;
    const bool lslot = tid < 126;
    const int gh = h_base - 1 + lr;
    const bool lvalid = lslot && ((unsigned)gh < 56u);
    const int goff = gh * 56 + cg * 4;
    const int soff = lr * 68 + 4 + cg * 4;

    const float* xn = x + n * 200704;
    const float4 z4 = make_float4(0.f, 0.f, 0.f, 0.f);
    float4 st[4] = {z4, z4, z4, z4};
    if (lvalid) {
#pragma unroll
        for (int cc = 0; cc < 4; cc++) st[cc] = *(const float4*)(xn + cc * 3136 + goff);
    }

    // compute layout: 16-lane rows
    const int wi = tid & 15;           // 0..15 (14..15 pad)
    const int row = tid >> 4;          // 0..7 (7 pad)
    const int crow = (row < 7) ? row : 6;  // clamped read row (pads duplicate row 6)
    const bool valid_out = (row < 7) && (wi < 14);
    const int w0 = 4 * wi;             // 0..60; col 4+w0+3 <= 67 in-bounds

    ull acc[4][2];
#pragma unroll
    for (int p = 0; p < 4; p++) { acc[p][0] = 0ull; acc[p][1] = 0ull; }

    for (int s = 0; s < 16; s++) {
        const int c0 = s * 4;
        float* tb = s_tile[s & 1];
        if (lslot) {
#pragma unroll
            for (int cc = 0; cc < 4; cc++) *(float4*)(tb + cc * CH_STRIDE + soff) = st[cc];
        }
        __syncthreads();
        if (s < 15 && lvalid) {
            const float* src = xn + (c0 + 4) * 3136 + goff;
#pragma unroll
            for (int cc = 0; cc < 4; cc++) st[cc] = *(const float4*)(src + cc * 3136);
        }
        // ALL threads execute (shuffle participation); pads read valid smem.
#pragma unroll
        for (int cc = 0; cc < 4; cc++) {
#pragma unroll
            for (int r = 0; r < 3; r++) {
                const float* rp = tb + cc * CH_STRIDE + (crow + r) * 68 + 4 + w0;
                float4 q = *(const float4*)rp;
                // halo via shuffle: vl = prev lane's q.w (0 at wi==0 = true halo);
                // vr = next lane's q.x (wi==13 pulls lane14's q.x = zeroed col 60).
                float vl = __shfl_up_sync(0xffffffffu, q.w, 1, 16);
                vl = (wi == 0) ? 0.f : vl;
                float vr = __shfl_down_sync(0xffffffffu, q.x, 1, 16);
                ull p0 = pack2(vl, vl), p1 = pack2(q.x, q.x), p2 = pack2(q.y, q.y);
                ull p3 = pack2(q.z, q.z), p4 = pack2(q.w, q.w), p5 = pack2(vr, vr);
                ulonglong2 t0 = *(const ulonglong2*)&s_w[c0 + cc][r * 3 + 0][0];
                ulonglong2 t1 = *(const ulonglong2*)&s_w[c0 + cc][r * 3 + 1][0];
                ulonglong2 t2 = *(const ulonglong2*)&s_w[c0 + cc][r * 3 + 2][0];
                ull wl, wh;
                wl = t0.x; wh = t0.y;
                acc[0][0] = fma2(p0, wl, acc[0][0]); acc[1][0] = fma2(p1, wl, acc[1][0]);
                acc[2][0] = fma2(p2, wl, acc[2][0]); acc[3][0] = fma2(p3, wl, acc[3][0]);
                acc[0][1] = fma2(p0, wh, acc[0][1]); acc[1][1] = fma2(p1, wh, acc[1][1]);
                acc[2][1] = fma2(p2, wh, acc[2][1]); acc[3][1] = fma2(p3, wh, acc[3][1]);
                wl = t1.x; wh = t1.y;
                acc[0][0] = fma2(p1, wl, acc[0][0]); acc[1][0] = fma2(p2, wl, acc[1][0]);
                acc[2][0] = fma2(p3, wl, acc[2][0]); acc[3][0] = fma2(p4, wl, acc[3][0]);
                acc[0][1] = fma2(p1, wh, acc[0][1]); acc[1][1] = fma2(p2, wh, acc[1][1]);
                acc[2][1] = fma2(p3, wh, acc[2][1]); acc[3][1] = fma2(p4, wh, acc[3][1]);
                wl = t2.x; wh = t2.y;
                acc[0][0] = fma2(p2, wl, acc[0][0]); acc[1][0] = fma2(p3, wl, acc[1][0]);
                acc[2][0] = fma2(p4, wl, acc[2][0]); acc[3][0] = fma2(p5, wl, acc[3][0]);
                acc[0][1] = fma2(p2, wh, acc[0][1]); acc[1][1] = fma2(p3, wh, acc[1][1]);
                acc[2][1] = fma2(p4, wh, acc[2][1]); acc[3][1] = fma2(p5, wh, acc[3][1]);
            }
        }
    }

    // tiles dead; alias buffer 0 for attn (barrier orders last reads vs writes)
    __syncthreads();
    float* s_attn = s_tile[0];  // [head*392 + px]

    if (valid_out) {
        float b0 = attn_b[0], b1 = attn_b[1], b2 = attn_b[2], b3v = attn_b[3];
#pragma unroll
        for (int p = 0; p < 4; p++) {
            float a0, a1, a2, a3;
            unpack2(acc[p][0], a0, a1);
            unpack2(acc[p][1], a2, a3);
            a0 = fmaxf(a0 + b0, 0.f);
            a1 = fmaxf(a1 + b1, 0.f);
            a2 = fmaxf(a2 + b2, 0.f);
            a3 = fmaxf(a3 + b3v, 0.f);
            int px = row * 56 + w0 + p;
            s_attn[0 * 392 + px] = sigmoid_exact(a0);
            s_attn[1 * 392 + px] = sigmoid_exact(a1);
            s_attn[2 * 392 + px] = sigmoid_exact(a2);
            s_attn[3 * 392 + px] = sigmoid_exact(a3);
        }
    }
    __syncthreads();

    // phase 2: x2 = x * attn, BN partial sums (4 full warps)
    const int warp = tid >> 5, lane = tid & 31;
    const int pidx = n * 8 + blockIdx.y;
    for (int c = warp; c < 64; c += 4) {
        int head = c >> 4;
        const float4* xp = (const float4*)(xn + c * 3136 + h_base * 56);
        float4* x2p = (float4*)(g_x2 + n * 200704 + c * 3136 + h_base * 56);
        const float4* ap = (const float4*)&s_attn[head * 392];
        float sum = 0.f, sq = 0.f;
        for (int i = lane; i < 98; i += 32) {
            float4 xv = xp[i], av = ap[i];
            float4 v;
            v.x = xv.x * av.x;
            v.y = xv.y * av.y;
            v.z = xv.z * av.z;
            v.w = xv.w * av.w;
            x2p[i] = v;
            sum += (v.x + v.y) + (v.z + v.w);
            sq += (v.x * v.x + v.y * v.y) + (v.z * v.z + v.w * v.w);
        }
#pragma unroll
        for (int o = 16; o; o >>= 1) {
            sum += __shfl_down_sync(0xffffffffu, sum, o);
            sq += __shfl_down_sync(0xffffffffu, sq, o);
        }
        if (lane == 0) {
            g_psum[c * 1024 + pidx] = sum;
            g_psq[c * 1024 + pidx] = sq;
        }
    }
}

// =====================================================================
// Kernel B: reduce BN partials -> scale/bias. grid 64, block 32.
// =====================================================================
__global__ void kernelB(const float* __restrict__ gamma, const float* __restrict__ beta) {
    int c = blockIdx.x, lane = threadIdx.x;
    float s = 0.f, q = 0.f;
    for (int i = lane; i < 1024; i += 32) {
        s += g_psum[c * 1024 + i];
        q += g_psq[c * 1024 + i];
    }
#pragma unroll
    for (int o = 16; o; o >>= 1) {
        s += __shfl_down_sync(0xffffffffu, s, o);
        q += __shfl_down_sync(0xffffffffu, q, o);
    }
    if (lane == 0) {
        const float inv_n = 1.f / 401408.f;
        float mean = s * inv_n;
        float var = q * inv_n - mean * mean;
        float sc = gamma[c] * rsqrtf(var + EPS);
        g_scale[c] = sc;
        g_bias[c] = beta[c] - mean * sc;
    }
}

// ---------------- 8-wide conv helpers (C): per-row paired weight loads ----------------
__device__ __forceinline__ void load_wrow(const ull* wv, int r, ull* wr) {
    if (r == 0) {
        ulonglong2 a = *(const ulonglong2*)&wv[0];
        wr[0] = a.x; wr[1] = a.y; wr[2] = wv[2];
    } else if (r == 1) {
        wr[0] = wv[3];
        ulonglong2 a = *(const ulonglong2*)&wv[4];
        wr[1] = a.x; wr[2] = a.y;
    } else {
        ulonglong2 a = *(const ulonglong2*)&wv[6];
        wr[0] = a.x; wr[1] = a.y; wr[2] = wv[8];
    }
}

__device__ __forceinline__ void conv_pair8(const float* tb, const ull (*wt)[12],
                                           int hi, int wi, ull* acc) {
#pragma unroll
    for (int cc = 0; cc < 4; cc++) {
        const ull* wv = wt[cc];
#pragma unroll
        for (int r = 0; r < 3; r++) {
            const float* rp = tb + cc * CH16 + (hi + r) * 68 + 4 + 8 * wi;
            float4 q0 = *(const float4*)rp;
            float4 q1 = *(const float4*)(rp + 4);
            float vl = rp[-1], vr = rp[8];
            ull p[10];
            p[0] = pack2(vl, vl);
            p[1] = pack2(q0.x, q0.x); p[2] = pack2(q0.y, q0.y);
            p[3] = pack2(q0.z, q0.z); p[4] = pack2(q0.w, q0.w);
            p[5] = pack2(q1.x, q1.x); p[6] = pack2(q1.y, q1.y);
            p[7] = pack2(q1.z, q1.z); p[8] = pack2(q1.w, q1.w);
            p[9] = pack2(vr, vr);
            ull wr[3];
            load_wrow(wv, r, wr);
#pragma unroll
            for (int jw = 0; jw < 3; jw++) {
                ull w = wr[jw];
#pragma unroll
                for (int o = 0; o < 8; o++) acc[o] = fma2(p[o + jw], w, acc[o]);
            }
        }
    }
}

__device__ __forceinline__ void conv_two8(const float* tb, const ull (*wtA)[12],
                                          const ull (*wtB)[12], int hi, int wi,
                                          ull* accA, ull* accB) {
#pragma unroll
    for (int cc = 0; cc < 4; cc++) {
        const ull* wvA = wtA[cc];
        const ull* wvB = wtB[cc];
#pragma unroll
        for (int r = 0; r < 3; r++) {
            const float* rp = tb + cc * CH16 + (hi + r) * 68 + 4 + 8 * wi;
            float4 q0 = *(const float4*)rp;
            float4 q1 = *(const float4*)(rp + 4);
            float vl = rp[-1], vr = rp[8];
            ull p[10];
            p[0] = pack2(vl, vl);
            p[1] = pack2(q0.x, q0.x); p[2] = pack2(q0.y, q0.y);
            p[3] = pack2(q0.z, q0.z); p[4] = pack2(q0.w, q0.w);
            p[5] = pack2(q1.x, q1.x); p[6] = pack2(q1.y, q1.y);
            p[7] = pack2(q1.z, q1.z); p[8] = pack2(q1.w, q1.w);
            p[9] = pack2(vr, vr);
            ull wrA[3], wrB[3];
            load_wrow(wvA, r, wrA);
            load_wrow(wvB, r, wrB);
#pragma unroll
            for (int jw = 0; jw < 3; jw++) {
                ull wa = wrA[jw], wb = wrB[jw];
#pragma unroll
                for (int o = 0; o < 8; o++) accA[o] = fma2(p[o + jw], wa, accA[o]);
#pragma unroll
                for (int o = 0; o < 8; o++) accB[o] = fma2(p[o + jw], wb, accB[o]);
            }
        }
    }
}

// =====================================================================
// Kernel C: grouped conv3d partials on relu(bn(x2)). t-QUAD + 4-way
// CHANNEL-SPLIT (8 of 32 ch per block) + 14-row tiles, 1h x 8w/thread.
// grid (128 [b*8+quad*4+cs], 2 g, 4 hz) = 1024 blocks, block 128.
// (R15-proven, unchanged)
// =====================================================================
__global__ void __launch_bounds__(128) kernelC(const float* __restrict__ w3) {
    __shared__ __align__(16) ull s_wp[4][8][12];
    __shared__ __align__(16) float s_tile[2][4 * CH16 + 8];
    __shared__ float s_sc[8], s_bi[8];

    const int bx = blockIdx.x;
    const int b = bx >> 3;
    const int quad = (bx >> 2) & 1;
    const int cs = bx & 3;
    const int t0 = quad * 4;
    const int g = blockIdx.y;
    const int h_base = blockIdx.z * 14;
    const int tid = threadIdx.x;
    const int gbase_ch = g * 32 + cs * 8;

    for (int i = tid; i < 72; i += 128) {
        int c = i / 9, k = i - (i / 9) * 9;
        int base = g * 864 + (cs * 8 + c) * 27;
        float w0v = w3[base + k];
        float w1v = w3[base + 9 + k];
        float w2v = w3[base + 18 + k];
        s_wp[0][c][k] = pack2(w0v, 0.f);
        s_wp[1][c][k] = pack2(w1v, w0v);
        s_wp[2][c][k] = pack2(w2v, w1v);
        s_wp[3][c][k] = pack2(0.f, w2v);
    }
    if (tid < 8) {
        s_sc[tid] = g_scale[gbase_ch + tid];
        s_bi[tid] = g_bias[gbase_ch + tid];
    }
    for (int i = tid; i < 128; i += 128) {
        int buf = i >> 6, rem = i & 63;
        float* row = &s_tile[buf][rem * 68];
        row[3] = 0.f;
        row[60] = 0.f;
    }
    // CRITICAL: stage-0 tile-write reads s_sc/s_bi (written by tid<8 only).
    __syncthreads();

    const int r0 = tid / 14, cg0 = tid - (tid / 14) * 14;
    const int i1 = tid + 128;
    const bool slot1 = i1 < 224;
    const int r1 = i1 / 14, cg1 = i1 - (i1 / 14) * 14;
    const int gh0 = h_base - 1 + r0, gh1 = h_base - 1 + r1;
    const bool v0 = (unsigned)gh0 < 56u;
    const bool v1 = slot1 && ((unsigned)gh1 < 56u);
    const int go0 = gh0 * 56 + cg0 * 4, go1 = gh1 * 56 + cg1 * 4;
    const int so0 = r0 * 68 + 4 + cg0 * 4, so1 = r1 * 68 + 4 + cg1 * 4;

    const int i_lo = (t0 == 0) ? 1 : 0;
    const float4 z4 = make_float4(0.f, 0.f, 0.f, 0.f);
    float4 st0[4] = {z4, z4, z4, z4}, st1[4] = {z4, z4, z4, z4};
    {
        int ts = t0 - 1 + i_lo;
        const float* src = g_x2 + ((b * 8 + ts) * 64 + gbase_ch) * 3136;
#pragma unroll
        for (int cc = 0; cc < 4; cc++) {
            if (v0) st0[cc] = *(const float4*)(src + cc * 3136 + go0);
            if (v1) st1[cc] = *(const float4*)(src + cc * 3136 + go1);
        }
    }

    const bool active = tid < 98;
    const int hi = tid / 7, wi = tid - (tid / 7) * 7;

    ull accA[8], accB[8];
#pragma unroll
    for (int o = 0; o < 8; o++) { accA[o] = 0ull; accB[o] = 0ull; }

    for (int s = 0; s < 10; s++) {
        const int i_sl = i_lo + (s >> 1);
        const int c0 = (s & 1) * 4;
        float* tb = s_tile[s & 1];
#pragma unroll
        for (int cc = 0; cc < 4; cc++) {
            float sc = s_sc[c0 + cc], bi = s_bi[c0 + cc];
            float4 v = z4;
            if (v0) {
                v.x = fmaxf(fmaf(st0[cc].x, sc, bi), 0.f);
                v.y = fmaxf(fmaf(st0[cc].y, sc, bi), 0.f);
                v.z = fmaxf(fmaf(st0[cc].z, sc, bi), 0.f);
                v.w = fmaxf(fmaf(st0[cc].w, sc, bi), 0.f);
            }
            *(float4*)(tb + cc * CH16 + so0) = v;
            if (slot1) {
                float4 u = z4;
                if (v1) {
                    u.x = fmaxf(fmaf(st1[cc].x, sc, bi), 0.f);
                    u.y = fmaxf(fmaf(st1[cc].y, sc, bi), 0.f);
                    u.z = fmaxf(fmaf(st1[cc].z, sc, bi), 0.f);
                    u.w = fmaxf(fmaf(st1[cc].w, sc, bi), 0.f);
                }
                *(float4*)(tb + cc * CH16 + so1) = u;
            }
        }
        __syncthreads();
        if (s < 9) {
            int i_n = i_lo + ((s + 1) >> 1);
            int tsn = t0 - 1 + i_n;
            int c0n = ((s + 1) & 1) * 4;
            const float* src = g_x2 + ((b * 8 + tsn) * 64 + gbase_ch + c0n) * 3136;
#pragma unroll
            for (int cc = 0; cc < 4; cc++) {
                if (v0) st0[cc] = *(const float4*)(src + cc * 3136 + go0);
                if (v1) st1[cc] = *(const float4*)(src + cc * 3136 + go1);
            }
        }
        if (active) {
            const int jA = i_sl;
            const int jB = i_sl - 2;
            const bool aon = (jA <= 3), bon = (jB >= 0);
            if (aon && bon)
                conv_two8(tb, &s_wp[jA][c0], &s_wp[jB][c0], hi, wi, accA, accB);
            else if (aon)
                conv_pair8(tb, &s_wp[jA][c0], hi, wi, accA);
            else
                conv_pair8(tb, &s_wp[jB][c0], hi, wi, accB);
        }
    }

    if (active) {
        int hw = (h_base + hi) * 56 + 8 * wi;
        float* gp = g_gpart[cs] + (((g * 16 + b) * 8 + t0) * 3136 + hw);
        float oa0[8], oa1[8], ob0[8], ob1[8];
#pragma unroll
        for (int o = 0; o < 8; o++) {
            unpack2(accA[o], oa0[o], oa1[o]);
            unpack2(accB[o], ob0[o], ob1[o]);
        }
        *(float4*)(gp + 0) = make_float4(oa0[0], oa0[1], oa0[2], oa0[3]);
        *(float4*)(gp + 4) = make_float4(oa0[4], oa0[5], oa0[6], oa0[7]);
        *(float4*)(gp + 3136) = make_float4(oa1[0], oa1[1], oa1[2], oa1[3]);
        *(float4*)(gp + 3140) = make_float4(oa1[4], oa1[5], oa1[6], oa1[7]);
        *(float4*)(gp + 2 * 3136) = make_float4(ob0[0], ob0[1], ob0[2], ob0[3]);
        *(float4*)(gp + 2 * 3136 + 4) = make_float4(ob0[4], ob0[5], ob0[6], ob0[7]);
        *(float4*)(gp + 3 * 3136) = make_float4(ob1[0], ob1[1], ob1[2], ob1[3]);
        *(float4*)(gp + 3 * 3136 + 4) = make_float4(ob1[4], ob1[5], ob1[6], ob1[7]);
    }
}

// =====================================================================
// Kernel C2: gate = tanhf(sum of 4 partials + bias). grid 3136, block 256.
// =====================================================================
__global__ void __launch_bounds__(256) kernelC2(const float* __restrict__ b3) {
    int idx = blockIdx.x * 256 + threadIdx.x;
    int g = idx / 401408;
    float v = (g_gpart[0][idx] + g_gpart[1][idx]) +
              (g_gpart[2][idx] + g_gpart[3][idx]) + b3[g];
    g_gate[idx] = tanhf(v);
}

// =====================================================================
// Kernel D: gate apply + temporal shift + channel interleave, float4 streaming.
// =====================================================================
__global__ void __launch_bounds__(256) kernelD(float* __restrict__ out) {
    int idx = blockIdx.x * 256 + threadIdx.x;
    int w4 = idx % 14;
    int tmp = idx / 14;
    int h = tmp % 56;
    tmp /= 56;
    int c_out = tmp & 63;
    int b = tmp >> 6;

    int gsel = c_out >> 5;
    int cc = c_out & 31;
    int c_src = gsel * 32 + (cc & 1) * 16 + (cc >> 1);

    int hw = h * 56 + w4 * 4;
    const float4* gbase = (const float4*)(g_gate + ((gsel * 16 + b) * 8) * 3136 + hw);
    int xoff0 = (b * 8) * 64 * 3136 + c_src * 3136 + hw;
    int ooff0 = (b * 8) * 64 * 3136 + c_out * 3136 + hw;

    float4 py = make_float4(0.f, 0.f, 0.f, 0.f);
    if (gsel == 0) {
#pragma unroll
        for (int t = 7; t >= 0; --t) {
            float4 xt = *(const float4*)(g_x2 + xoff0 + t * 64 * 3136);
            float4 gt = gbase[t * 784];
            float4 o;
            o.x = py.x + (1.f - gt.x) * xt.x;
            o.y = py.y + (1.f - gt.y) * xt.y;
            o.z = py.z + (1.f - gt.z) * xt.z;
            o.w = py.w + (1.f - gt.w) * xt.w;
            *(float4*)(out + ooff0 + t * 64 * 3136) = o;
            py.x = gt.x * xt.x;
            py.y = gt.y * xt.y;
            py.z = gt.z * xt.z;
            py.w = gt.w * xt.w;
        }
    } else {
#pragma unroll
        for (int t = 0; t < 8; ++t) {
            float4 xt = *(const float4*)(g_x2 + xoff0 + t * 64 * 3136);
            float4 gt = gbase[t * 784];
            float4 o;
            o.x = py.x + (1.f - gt.x) * xt.x;
            o.y = py.y + (1.f - gt.y) * xt.y;
            o.z = py.z + (1.f - gt.z) * xt.z;
            o.w = py.w + (1.f - gt.w) * xt.w;
            *(float4*)(out + ooff0 + t * 64 * 3136) = o;
            py.x = gt.x * xt.x;
            py.y = gt.y * xt.y;
            py.z = gt.z * xt.z;
            py.w = gt.w * xt.w;
        }
    }
}

// =====================================================================
extern "C" void kernel_launch(void* const* d_in, const int* in_sizes, int n_in,
                              void* d_out, int out_size) {
    const float* x = (const float*)d_in[0];
    const float* attn_w = (const float*)d_in[1];
    const float* attn_b = (const float*)d_in[2];
    const float* gamma = (const float*)d_in[3];
    const float* beta = (const float*)d_in[4];
    const float* w3 = (const float*)d_in[5];
    const float* b3 = (const float*)d_in[6];
    float* out = (float*)d_out;

    // 3 nops: ncu (-s 5 -c 1, 2 harness pre-launches) captures kernelA
    kNop<<<1, 32>>>();
    kNop<<<1, 32>>>();
    kNop<<<1, 32>>>();
    kernelA<<<dim3(128, 8), 128>>>(x, attn_w, attn_b);
    kernelB<<<64, 32>>>(gamma, beta);
    kernelC<<<dim3(128, 2, 4), 128>>>(w3);
    kernelC2<<<3136, 256>>>(b3);
    kernelD<<<3136, 256>>>(out);
}